// round 1
// baseline (speedup 1.0000x reference)
#include <cuda_runtime.h>
#include <cuda_bf16.h>

// Problem constants
#define BB 2
#define NN 4096
#define MM 12288
#define HH 8
#define DD 256      // DV = DE = 256
#define DKH 32      // per-head dim
#define KNB 16      // KV = KE = 16
#define LN_EPS 1e-5f

// ---------------- scratch (no allocations allowed) ----------------
// Layout (floats):
//  vQ [B*N*D]  vK [B*N*D]  vV [B*N*D]
//  eQ [B*M*D]  eK [B*M*D]
//  t1 [B*M*D]  t2 [B*M*D]  t3 [B*N*D]
#define OFF_VQ 0L
#define OFF_VK 2097152L
#define OFF_VV 4194304L
#define OFF_EQ 6291456L
#define OFF_EK 12582912L
#define OFF_T1 18874368L
#define OFF_T2 25165824L
#define OFF_T3 31457280L
__device__ float g_scratch[33554432];  // 128 MB

// ---------------- SGEMM: C[row,col] = sum_k A(row,k) * B(k,col) ----------------
// TA: A(row,k) = A[k*lda + row]   (else A[row*lda + k])
// TB: B(k,col) = B[col*ldb + k]   (else B[k*ldb + col])
// Tiles: 128x128x16, 256 threads, 8x8 per thread. All dims divide evenly.
#define TBM 128
#define TBN 128
#define TBK 16

template <bool TA, bool TB>
__global__ __launch_bounds__(256, 2)
void sgemm_kernel(const float* __restrict__ A, const float* __restrict__ Bm,
                  float* __restrict__ C,
                  int Mr, int Nc, int K,
                  int lda, int ldb, int ldc,
                  long strideA, long strideB, long strideC)
{
    __shared__ float As[TBK][TBM];
    __shared__ float Bs[TBK][TBN];

    const float* Ab = A + (long)blockIdx.z * strideA;
    const float* Bb = Bm + (long)blockIdx.z * strideB;
    float* Cb = C + (long)blockIdx.z * strideC;

    const int row0 = blockIdx.y * TBM;
    const int col0 = blockIdx.x * TBN;
    const int tid = threadIdx.x;
    const int tx = tid & 15;
    const int ty = tid >> 4;

    float acc[8][8];
#pragma unroll
    for (int i = 0; i < 8; i++)
#pragma unroll
        for (int j = 0; j < 8; j++) acc[i][j] = 0.f;

    for (int k0 = 0; k0 < K; k0 += TBK) {
        // ---- load A tile ----
        if (!TA) {
#pragma unroll
            for (int i = 0; i < 2; i++) {
                int t = tid + i * 256;          // 0..511
                int r = t >> 2;                  // 0..127
                int kk4 = (t & 3) << 2;          // 0,4,8,12
                float4 v = *(const float4*)(Ab + (long)(row0 + r) * lda + (k0 + kk4));
                As[kk4 + 0][r] = v.x; As[kk4 + 1][r] = v.y;
                As[kk4 + 2][r] = v.z; As[kk4 + 3][r] = v.w;
            }
        } else {
#pragma unroll
            for (int i = 0; i < 2; i++) {
                int t = tid + i * 256;
                int kk = t >> 5;                 // 0..15
                int r4 = (t & 31) << 2;          // 0..124
                float4 v = *(const float4*)(Ab + (long)(k0 + kk) * lda + (row0 + r4));
                *(float4*)&As[kk][r4] = v;
            }
        }
        // ---- load B tile ----
        if (!TB) {
#pragma unroll
            for (int i = 0; i < 2; i++) {
                int t = tid + i * 256;
                int kk = t >> 5;
                int c4 = (t & 31) << 2;
                float4 v = *(const float4*)(Bb + (long)(k0 + kk) * ldb + (col0 + c4));
                *(float4*)&Bs[kk][c4] = v;
            }
        } else {
#pragma unroll
            for (int i = 0; i < 2; i++) {
                int t = tid + i * 256;
                int c = t >> 2;                  // 0..127
                int kk4 = (t & 3) << 2;
                float4 v = *(const float4*)(Bb + (long)(col0 + c) * ldb + (k0 + kk4));
                Bs[kk4 + 0][c] = v.x; Bs[kk4 + 1][c] = v.y;
                Bs[kk4 + 2][c] = v.z; Bs[kk4 + 3][c] = v.w;
            }
        }
        __syncthreads();

#pragma unroll
        for (int kk = 0; kk < TBK; kk++) {
            float4 a0 = *(const float4*)&As[kk][ty * 8];
            float4 a1 = *(const float4*)&As[kk][ty * 8 + 4];
            float4 b0 = *(const float4*)&Bs[kk][tx * 8];
            float4 b1 = *(const float4*)&Bs[kk][tx * 8 + 4];
            float a[8] = {a0.x, a0.y, a0.z, a0.w, a1.x, a1.y, a1.z, a1.w};
            float b[8] = {b0.x, b0.y, b0.z, b0.w, b1.x, b1.y, b1.z, b1.w};
#pragma unroll
            for (int i = 0; i < 8; i++)
#pragma unroll
                for (int j = 0; j < 8; j++)
                    acc[i][j] = fmaf(a[i], b[j], acc[i][j]);
        }
        __syncthreads();
    }

#pragma unroll
    for (int i = 0; i < 8; i++) {
        int r = row0 + ty * 8 + i;
        float4* cp = (float4*)(Cb + (long)r * ldc + col0 + tx * 8);
        cp[0] = make_float4(acc[i][0], acc[i][1], acc[i][2], acc[i][3]);
        cp[1] = make_float4(acc[i][4], acc[i][5], acc[i][6], acc[i][7]);
    }
}

// ---------------- LayerNorm over contiguous 32-element groups ----------------
__global__ void layernorm32_kernel(float* __restrict__ x, int ngroups)
{
    int g = blockIdx.x * 8 + (threadIdx.x >> 5);
    int lane = threadIdx.x & 31;
    if (g >= ngroups) return;
    long base = (long)g * 32 + lane;
    float v = x[base];
    float mu = v;
#pragma unroll
    for (int o = 16; o > 0; o >>= 1) mu += __shfl_xor_sync(0xffffffffu, mu, o);
    mu *= (1.0f / 32.0f);
    float d = v - mu;
    float var = d * d;
#pragma unroll
    for (int o = 16; o > 0; o >>= 1) var += __shfl_xor_sync(0xffffffffu, var, o);
    var *= (1.0f / 32.0f);
    x[base] = d * rsqrtf(var + LN_EPS);
}

// ---------------- sparse attention ----------------
// out[b,row,h,:] = softmax_j( q[b,row,h,:].k[b,idx[row,j],h,:] / sqrt(32) ) . x[b,idx[row,j],h,:]
// One block per (row, b); 8 warps = 8 heads; lane = head dim.
__global__ __launch_bounds__(256)
void sparse_attn_kernel(const float* __restrict__ xg,
                        const float* __restrict__ q,
                        const float* __restrict__ kmat,
                        const int* __restrict__ idx,
                        float* __restrict__ out,
                        int rows)
{
    int row = blockIdx.x;
    int b = blockIdx.y;
    int h = threadIdx.x >> 5;
    int lane = threadIdx.x & 31;

    __shared__ int sidx[KNB];
    if (threadIdx.x < KNB) sidx[threadIdx.x] = idx[row * KNB + threadIdx.x];
    __syncthreads();

    long base = ((long)b * rows + row) * DD + h * DKH;
    float qv = q[base + lane];

    float s[KNB];
#pragma unroll
    for (int j = 0; j < KNB; j++) {
        long nb = ((long)b * rows + sidx[j]) * DD + h * DKH;
        float d = qv * kmat[nb + lane];
#pragma unroll
        for (int o = 16; o > 0; o >>= 1) d += __shfl_xor_sync(0xffffffffu, d, o);
        s[j] = d * 0.17677669529663687f;  // 1/sqrt(32)
    }
    float mx = s[0];
#pragma unroll
    for (int j = 1; j < KNB; j++) mx = fmaxf(mx, s[j]);
    float sum = 0.f;
#pragma unroll
    for (int j = 0; j < KNB; j++) { s[j] = __expf(s[j] - mx); sum += s[j]; }
    float inv = 1.0f / sum;
    float o = 0.f;
#pragma unroll
    for (int j = 0; j < KNB; j++) {
        long nb = ((long)b * rows + sidx[j]) * DD + h * DKH;
        o = fmaf(s[j], xg[nb + lane], o);
    }
    out[base + lane] = o * inv;
}

// ---------------- launch ----------------
extern "C" void kernel_launch(void* const* d_in, const int* in_sizes, int n_in,
                              void* d_out, int out_size)
{
    const float* x_v  = (const float*)d_in[0];   // (B,N,256)
    const float* x_e  = (const float*)d_in[1];   // (B,M,256)
    const float* d_0  = (const float*)d_in[2];   // (B,M,N)
    const float* W_vQ = (const float*)d_in[3];   // (256,256)
    const float* W_vK = (const float*)d_in[4];
    const float* W_vV = (const float*)d_in[5];
    const float* W_eQ = (const float*)d_in[6];
    const float* W_eK = (const float*)d_in[7];
    const int*   v_idx = (const int*)d_in[8];    // (N,16)
    const int*   e_idx = (const int*)d_in[9];    // (M,16)
    float* out = (float*)d_out;

    float* base;
    cudaGetSymbolAddress((void**)&base, g_scratch);
    float* vQ = base + OFF_VQ;
    float* vK = base + OFF_VK;
    float* vV = base + OFF_VV;
    float* eQ = base + OFF_EQ;
    float* eK = base + OFF_EK;
    float* t1 = base + OFF_T1;
    float* t2 = base + OFF_T2;
    float* t3 = base + OFF_T3;

    // 1) projections: rows fold batch; C[r,e] = sum_d X[r,d] * W[e,d]  (TB=true)
    {
        dim3 gv(DD / TBN, (BB * NN) / TBM, 1);
        sgemm_kernel<false, true><<<gv, 256>>>(x_v, W_vQ, vQ, BB * NN, DD, DD, DD, DD, DD, 0, 0, 0);
        sgemm_kernel<false, true><<<gv, 256>>>(x_v, W_vK, vK, BB * NN, DD, DD, DD, DD, DD, 0, 0, 0);
        sgemm_kernel<false, true><<<gv, 256>>>(x_v, W_vV, vV, BB * NN, DD, DD, DD, DD, DD, 0, 0, 0);
        dim3 ge(DD / TBN, (BB * MM) / TBM, 1);
        sgemm_kernel<false, true><<<ge, 256>>>(x_e, W_eQ, eQ, BB * MM, DD, DD, DD, DD, DD, 0, 0, 0);
        sgemm_kernel<false, true><<<ge, 256>>>(x_e, W_eK, eK, BB * MM, DD, DD, DD, DD, DD, 0, 0, 0);
    }

    // 2) layernorm (per 32-elem head group) on vQ, vK, eQ, eK
    {
        int gv = BB * NN * HH;   // 65536
        int ge = BB * MM * HH;   // 196608
        layernorm32_kernel<<<gv / 8, 256>>>(vQ, gv);
        layernorm32_kernel<<<gv / 8, 256>>>(vK, gv);
        layernorm32_kernel<<<ge / 8, 256>>>(eQ, ge);
        layernorm32_kernel<<<ge / 8, 256>>>(eK, ge);
    }

    // 3) t1[b,m,:] = sum_n d0[b,m,n] * vV[b,n,:]
    {
        dim3 g(DD / TBN, MM / TBM, BB);
        sgemm_kernel<false, false><<<g, 256>>>(d_0, vV, t1, MM, DD, NN,
                                               NN, DD, DD,
                                               (long)MM * NN, (long)NN * DD, (long)MM * DD);
    }

    // 4) sparse attention over e: x=t1, q=eQ, k=eK, idx=e_idx -> t2
    sparse_attn_kernel<<<dim3(MM, BB), 256>>>(t1, eQ, eK, e_idx, t2, MM);

    // 5) t3[b,n,:] = sum_m d0[b,m,n] * t2[b,m,:]   (A transposed access)
    {
        dim3 g(DD / TBN, NN / TBM, BB);
        sgemm_kernel<true, false><<<g, 256>>>(d_0, t2, t3, NN, DD, MM,
                                              NN, DD, DD,
                                              (long)MM * NN, (long)MM * DD, (long)NN * DD);
    }

    // 6) sparse attention over v: x=t3, q=vK, k=vQ, idx=v_idx -> out
    sparse_attn_kernel<<<dim3(NN, BB), 256>>>(t3, vK, vQ, v_idx, out, NN);
}